// round 2
// baseline (speedup 1.0000x reference)
#include <cuda_runtime.h>
#include <math.h>

// Problem constants
#define Bsz   2
#define Ssz   4096
#define Dsz   1024
#define Hn    4
#define DKn   128
#define DVn   256
#define KDn   512     // H*DK
#define VDn   1024    // H*DV
#define Csz   64
#define NCn   64      // S / C
#define RANKn 16
#define NROWS (Bsz*Ssz)   // 8192

// ---------------- scratch (device globals; no allocation allowed) -------------
__device__ float g_bufQ [NROWS*KDn];              // q (pre-scaled)
__device__ float g_bufK [NROWS*KDn];              // k
__device__ float g_bufV [NROWS*VDn];              // v
__device__ float g_bufG [NROWS*VDn];              // gate g
__device__ float g_bufGC[NROWS*KDn];              // gk then (in place) per-chunk cumsum
__device__ float g_bufT [NROWS*RANKn];            // low-rank intermediate
__device__ float g_bufA [Bsz*NCn*Hn*Csz*Csz];     // intra-chunk attention (masked)
__device__ float g_bufKV[Bsz*Hn*NCn*DKn*DVn];     // per-chunk kv outer products
__device__ float g_bufS [Bsz*Hn*NCn*DKn*DVn];     // state entering each chunk
__device__ float g_bufO [NROWS*VDn];              // attention output (pre-norm)
__device__ float g_bufZ [NROWS*VDn];              // normed+gated, input to final GEMM

__device__ __forceinline__ float* proj_out(int sel){
    switch(sel){
        case 0: return g_bufQ;
        case 1: return g_bufK;
        case 2: return g_bufV;
        default: return g_bufG;
    }
}

// ---------------- generic fp32 tiled GEMM: C[M,N] = alpha * A[M,K] @ B[K,N] ----
// 64x64 block tile, 16 K-step, 256 threads, 4x4 per thread. All dims multiples.
__device__ __forceinline__ void gemm_body(const float* __restrict__ A,
                                          const float* __restrict__ Bm,
                                          float* __restrict__ C,
                                          int N, int K, float alpha)
{
    __shared__ float sA[16][65];
    __shared__ float sB[16][65];
    const int bm = blockIdx.y * 64;
    const int bn = blockIdx.x * 64;
    const int tid = threadIdx.x;
    const int ty = tid >> 4, tx = tid & 15;
    float acc[4][4] = {};

    for (int k0 = 0; k0 < K; k0 += 16){
        #pragma unroll
        for (int rep = 0; rep < 4; rep++){
            int i = tid + rep*256;
            int r = i >> 4, c = i & 15;
            sA[c][r] = A[(size_t)(bm + r) * K + k0 + c];
        }
        #pragma unroll
        for (int rep = 0; rep < 4; rep++){
            int i = tid + rep*256;
            int r = i >> 6, c = i & 63;
            sB[r][c] = Bm[(size_t)(k0 + r) * N + bn + c];
        }
        __syncthreads();
        #pragma unroll
        for (int kk = 0; kk < 16; kk++){
            float a[4], b[4];
            #pragma unroll
            for (int u = 0; u < 4; u++){ a[u] = sA[kk][ty*4+u]; b[u] = sB[kk][tx*4+u]; }
            #pragma unroll
            for (int u = 0; u < 4; u++)
                #pragma unroll
                for (int w = 0; w < 4; w++)
                    acc[u][w] += a[u] * b[w];
        }
        __syncthreads();
    }
    #pragma unroll
    for (int u = 0; u < 4; u++)
        #pragma unroll
        for (int w = 0; w < 4; w++)
            C[(size_t)(bm + ty*4 + u) * N + bn + tx*4 + w] = alpha * acc[u][w];
}

__global__ void gemm_proj_kernel(const float* __restrict__ x,
                                 const float* __restrict__ W,
                                 int sel, int N, float alpha)
{
    gemm_body(x, W, proj_out(sel), N, Dsz, alpha);
}

__global__ void gemm_final_kernel(const float* __restrict__ Wo,
                                  float* __restrict__ out)
{
    gemm_body(g_bufZ, Wo, out, Dsz, VDn, 1.0f);
}

// ---------------- t = x @ Wgk1  ([8192,1024] @ [1024,16]) ----------------------
__global__ void gemm_t_kernel(const float* __restrict__ x,
                              const float* __restrict__ W)
{
    __shared__ float sA[16][65];
    __shared__ float sB[16][17];
    const int bm = blockIdx.x * 64;
    const int tid = threadIdx.x;
    const int ty = tid >> 4, tx = tid & 15;
    float acc[4] = {};
    for (int k0 = 0; k0 < Dsz; k0 += 16){
        #pragma unroll
        for (int rep = 0; rep < 4; rep++){
            int i = tid + rep*256;
            int r = i >> 4, c = i & 15;
            sA[c][r] = x[(size_t)(bm + r) * Dsz + k0 + c];
        }
        { // 16x16 weight tile
            int r = tid >> 4, c = tid & 15;
            sB[r][c] = W[(size_t)(k0 + r) * RANKn + c];
        }
        __syncthreads();
        #pragma unroll
        for (int kk = 0; kk < 16; kk++){
            float b = sB[kk][tx];
            #pragma unroll
            for (int u = 0; u < 4; u++)
                acc[u] += sA[kk][ty*4+u] * b;
        }
        __syncthreads();
    }
    #pragma unroll
    for (int u = 0; u < 4; u++)
        g_bufT[(size_t)(bm + ty*4 + u) * RANKn + tx] = acc[u];
}

// ---------------- gk = log_sigmoid(t @ Wgk2 + bgk) / 16 -----------------------
__global__ void gk_kernel(const float* __restrict__ Wgk2,
                          const float* __restrict__ bgk)
{
    const int col = blockIdx.x * 256 + threadIdx.x;   // 0..511
    const int row = blockIdx.y;
    __shared__ float st[RANKn];
    if (threadIdx.x < RANKn) st[threadIdx.x] = g_bufT[(size_t)row * RANKn + threadIdx.x];
    __syncthreads();
    float acc = bgk[col];
    #pragma unroll
    for (int r = 0; r < RANKn; r++)
        acc += st[r] * Wgk2[r * KDn + col];
    float ls = fminf(acc, 0.0f) - log1pf(expf(-fabsf(acc)));   // stable log_sigmoid
    g_bufGC[(size_t)row * KDn + col] = ls * (1.0f / 16.0f);
}

// ---------------- per-chunk cumsum of gk along time (in place) ----------------
__global__ void gcum_kernel()
{
    const int ch    = blockIdx.y * 256 + threadIdx.x;  // channel 0..511
    const int chunk = blockIdx.x;                      // 0..127 (b*NC+n)
    const int row0  = chunk * Csz;
    float s = 0.0f;
    for (int t = 0; t < Csz; t++){
        size_t idx = (size_t)(row0 + t) * KDn + ch;
        s += g_bufGC[idx];
        g_bufGC[idx] = s;
    }
}

// ---------------- intra-chunk A = tril( (q*e^g) @ (k*e^-g)^T ) -----------------
__global__ void attnA_kernel()
{
    const int chunk = blockIdx.x;        // 0..127
    const int h     = blockIdx.y;        // 0..3
    const int row0  = chunk * Csz;
    const int cb    = h * DKn;
    const int tid = threadIdx.x;
    const int ty = tid >> 4, tx = tid & 15;
    __shared__ float sq[16][65];
    __shared__ float sk[16][65];
    float acc[4][4] = {};
    for (int k0 = 0; k0 < DKn; k0 += 16){
        #pragma unroll
        for (int rep = 0; rep < 4; rep++){
            int i = tid + rep*256;
            int t = i >> 4, kk = i & 15;
            size_t idx = (size_t)(row0 + t) * KDn + cb + k0 + kk;
            float g = g_bufGC[idx];
            sq[kk][t] = g_bufQ[idx] * expf(g);
            sk[kk][t] = g_bufK[idx] * expf(-g);
        }
        __syncthreads();
        #pragma unroll
        for (int kk = 0; kk < 16; kk++){
            float a[4], b[4];
            #pragma unroll
            for (int u = 0; u < 4; u++){ a[u] = sq[kk][ty*4+u]; b[u] = sk[kk][tx*4+u]; }
            #pragma unroll
            for (int u = 0; u < 4; u++)
                #pragma unroll
                for (int w = 0; w < 4; w++)
                    acc[u][w] += a[u] * b[w];
        }
        __syncthreads();
    }
    #pragma unroll
    for (int u = 0; u < 4; u++)
        #pragma unroll
        for (int w = 0; w < 4; w++){
            int t = ty*4 + u, s = tx*4 + w;
            g_bufA[((size_t)(chunk*Hn + h) * Csz + t) * Csz + s] = (t >= s) ? acc[u][w] : 0.0f;
        }
}

// ---------------- per-chunk kv[k,v] = sum_s k_dec[s,k] * v[s,v] ----------------
__global__ void kv_kernel()
{
    const int chunk = blockIdx.x;         // 0..127
    const int h     = blockIdx.y;         // 0..3
    const int vb    = blockIdx.z;         // 0..3 (64 v-cols each)
    const int row0  = chunk * Csz;
    const int kc    = h * DKn;
    const int vc0   = h * DVn + vb * 64;
    const int n     = chunk & 63;
    const int bh    = (chunk >> 6) * Hn + h;
    const int tid = threadIdx.x;
    const int ty = tid >> 4, tx = tid & 15;

    __shared__ float skd[16][128];
    __shared__ float sv [16][65];
    __shared__ float gl [DKn];
    if (tid < DKn) gl[tid] = g_bufGC[(size_t)(row0 + Csz - 1) * KDn + kc + tid];
    __syncthreads();

    float acc[8][4] = {};
    for (int s0 = 0; s0 < Csz; s0 += 16){
        #pragma unroll
        for (int rep = 0; rep < 8; rep++){
            int i = tid + rep*256;
            int ss = i >> 7, kk = i & 127;
            size_t idx = (size_t)(row0 + s0 + ss) * KDn + kc + kk;
            skd[ss][kk] = g_bufK[idx] * expf(gl[kk] - g_bufGC[idx]);
        }
        #pragma unroll
        for (int rep = 0; rep < 4; rep++){
            int i = tid + rep*256;
            int ss = i >> 6, vv = i & 63;
            sv[ss][vv] = g_bufV[(size_t)(row0 + s0 + ss) * VDn + vc0 + vv];
        }
        __syncthreads();
        #pragma unroll
        for (int ss = 0; ss < 16; ss++){
            float a[8], b[4];
            #pragma unroll
            for (int u = 0; u < 8; u++) a[u] = skd[ss][ty*8+u];
            #pragma unroll
            for (int w = 0; w < 4; w++) b[w] = sv[ss][tx*4+w];
            #pragma unroll
            for (int u = 0; u < 8; u++)
                #pragma unroll
                for (int w = 0; w < 4; w++)
                    acc[u][w] += a[u] * b[w];
        }
        __syncthreads();
    }
    size_t base = ((size_t)(bh * NCn + n)) * DKn * DVn;
    #pragma unroll
    for (int u = 0; u < 8; u++)
        #pragma unroll
        for (int w = 0; w < 4; w++)
            g_bufKV[base + (size_t)(ty*8+u) * DVn + vb*64 + tx*4 + w] = acc[u][w];
}

// ---------------- inter-chunk scan: S_0=0; S_{n+1}=S_n*e^{gl_n}+kv_n ------------
__global__ void scan_kernel()
{
    const int bh   = blockIdx.x;                       // 0..7
    const int elem = blockIdx.y * 256 + threadIdx.x;   // 0..32767
    const int kk   = elem >> 8;                        // /256
    const int b    = bh / Hn, h = bh % Hn;
    float s = 0.0f;
    for (int n = 0; n < NCn; n++){
        size_t base = ((size_t)(bh * NCn + n)) * (DKn * DVn);
        g_bufS[base + elem] = s;
        float gl = g_bufGC[(size_t)((b * NCn + n) * Csz + Csz - 1) * KDn + h * DKn + kk];
        s = s * expf(gl) + g_bufKV[base + elem];
    }
}

// ---------------- o = A @ v_chunk + q_t @ S_n ----------------------------------
__global__ void out_kernel()
{
    const int chunk = blockIdx.x;         // 0..127
    const int h     = blockIdx.y;         // 0..3
    const int vb    = blockIdx.z;         // 0..3
    const int row0  = chunk * Csz;
    const int n     = chunk & 63;
    const int bh    = (chunk >> 6) * Hn + h;
    const int vcol  = h * DVn + vb * 64;
    const int tid = threadIdx.x;
    const int ty = tid >> 4, tx = tid & 15;

    __shared__ float sa[16][65];
    __shared__ float sb[16][65];
    float acc[4][4] = {};

    // intra: A[64,64] @ v[64,64]
    for (int s0 = 0; s0 < Csz; s0 += 16){
        #pragma unroll
        for (int rep = 0; rep < 4; rep++){
            int i = tid + rep*256;
            int t = i >> 4, ss = i & 15;
            sa[ss][t] = g_bufA[((size_t)(chunk*Hn + h) * Csz + t) * Csz + s0 + ss];
        }
        #pragma unroll
        for (int rep = 0; rep < 4; rep++){
            int i = tid + rep*256;
            int ss = i >> 6, vv = i & 63;
            sb[ss][vv] = g_bufV[(size_t)(row0 + s0 + ss) * VDn + vcol + vv];
        }
        __syncthreads();
        #pragma unroll
        for (int ss = 0; ss < 16; ss++){
            float a[4], b[4];
            #pragma unroll
            for (int u = 0; u < 4; u++){ a[u] = sa[ss][ty*4+u]; b[u] = sb[ss][tx*4+u]; }
            #pragma unroll
            for (int u = 0; u < 4; u++)
                #pragma unroll
                for (int w = 0; w < 4; w++)
                    acc[u][w] += a[u] * b[w];
        }
        __syncthreads();
    }

    // inter: q_t[64,128] @ S[128,64]
    const size_t sbase = ((size_t)(bh * NCn + n)) * (DKn * DVn);
    for (int k0 = 0; k0 < DKn; k0 += 16){
        #pragma unroll
        for (int rep = 0; rep < 4; rep++){
            int i = tid + rep*256;
            int t = i >> 4, kk = i & 15;
            size_t idx = (size_t)(row0 + t) * KDn + h * DKn + k0 + kk;
            sa[kk][t] = g_bufQ[idx] * expf(g_bufGC[idx]);
        }
        #pragma unroll
        for (int rep = 0; rep < 4; rep++){
            int i = tid + rep*256;
            int kk = i >> 6, vv = i & 63;
            sb[kk][vv] = g_bufS[sbase + (size_t)(k0 + kk) * DVn + vb*64 + vv];
        }
        __syncthreads();
        #pragma unroll
        for (int kk = 0; kk < 16; kk++){
            float a[4], b[4];
            #pragma unroll
            for (int u = 0; u < 4; u++){ a[u] = sa[kk][ty*4+u]; b[u] = sb[kk][tx*4+u]; }
            #pragma unroll
            for (int u = 0; u < 4; u++)
                #pragma unroll
                for (int w = 0; w < 4; w++)
                    acc[u][w] += a[u] * b[w];
        }
        __syncthreads();
    }

    #pragma unroll
    for (int u = 0; u < 4; u++)
        #pragma unroll
        for (int w = 0; w < 4; w++)
            g_bufO[(size_t)(row0 + ty*4 + u) * VDn + vcol + tx*4 + w] = acc[u][w];
}

// ---------------- RMS-norm over DV + SiLU gate ---------------------------------
// NOTE: norm_w has shape (DV,) = (256,) — shared across heads.
__global__ void norm_gate_kernel(const float* __restrict__ norm_w)
{
    const int row = blockIdx.x;
    const int h   = blockIdx.y;
    const int tid = threadIdx.x;   // 256 == DVn
    size_t idx = (size_t)row * VDn + h * DVn + tid;
    float o = g_bufO[idx];
    float sq = o * o;
    #pragma unroll
    for (int off = 16; off; off >>= 1) sq += __shfl_xor_sync(0xffffffffu, sq, off);
    __shared__ float ws[8];
    if ((tid & 31) == 0) ws[tid >> 5] = sq;
    __syncthreads();
    float tot = 0.0f;
    #pragma unroll
    for (int i = 0; i < 8; i++) tot += ws[i];
    float r = rsqrtf(tot * (1.0f / 256.0f) + 1e-5f);
    float gv = g_bufG[idx];
    float silu = gv / (1.0f + expf(-gv));
    g_bufZ[idx] = o * r * norm_w[tid] * silu;
}

// ---------------- launcher ------------------------------------------------------
extern "C" void kernel_launch(void* const* d_in, const int* in_sizes, int n_in,
                              void* d_out, int out_size)
{
    const float* x     = (const float*)d_in[0];
    const float* Wq    = (const float*)d_in[1];
    const float* Wk    = (const float*)d_in[2];
    const float* Wv    = (const float*)d_in[3];
    const float* Wgk1  = (const float*)d_in[4];
    const float* Wgk2  = (const float*)d_in[5];
    const float* bgk   = (const float*)d_in[6];
    const float* Wg    = (const float*)d_in[7];
    const float* Wo    = (const float*)d_in[8];
    const float* normw = (const float*)d_in[9];
    float* out = (float*)d_out;

    const float scale = 0.08838834764831845f;   // DK^-0.5 = 1/sqrt(128)
    dim3 blk(256);

    // projections
    gemm_proj_kernel<<<dim3(KDn/64, NROWS/64), blk>>>(x, Wq, 0, KDn, scale);
    gemm_proj_kernel<<<dim3(KDn/64, NROWS/64), blk>>>(x, Wk, 1, KDn, 1.0f);
    gemm_proj_kernel<<<dim3(VDn/64, NROWS/64), blk>>>(x, Wv, 2, VDn, 1.0f);
    gemm_proj_kernel<<<dim3(VDn/64, NROWS/64), blk>>>(x, Wg, 3, VDn, 1.0f);

    // low-rank gate path
    gemm_t_kernel<<<NROWS/64, blk>>>(x, Wgk1);
    gk_kernel<<<dim3(KDn/256, NROWS), blk>>>(Wgk2, bgk);
    gcum_kernel<<<dim3(Bsz*NCn, KDn/256), blk>>>();

    // GLA chunks
    attnA_kernel<<<dim3(Bsz*NCn, Hn), blk>>>();
    kv_kernel<<<dim3(Bsz*NCn, Hn, DVn/64), blk>>>();
    scan_kernel<<<dim3(Bsz*Hn, (DKn*DVn)/256), blk>>>();
    out_kernel<<<dim3(Bsz*NCn, Hn, DVn/64), blk>>>();

    // epilogue
    norm_gate_kernel<<<dim3(NROWS, Hn), blk>>>(normw);
    gemm_final_kernel<<<dim3(Dsz/64, NROWS/64), blk>>>(Wo, out);
}

// round 3
// speedup vs baseline: 1.0004x; 1.0004x over previous
#include <cuda_runtime.h>
#include <math.h>

// Problem constants
#define Bsz   2
#define Ssz   4096
#define Dsz   1024
#define Hn    4
#define DKn   128
#define DVn   256
#define KDn   512     // H*DK
#define VDn   1024    // H*DV
#define Csz   64
#define NCn   64      // S / C
#define RANKn 16
#define NROWS (Bsz*Ssz)   // 8192

// ---------------- scratch (device globals; no allocation allowed) -------------
__device__ float g_bufQ [NROWS*KDn];              // q (pre-scaled)
__device__ float g_bufK [NROWS*KDn];              // k
__device__ float g_bufV [NROWS*VDn];              // v
__device__ float g_bufG [NROWS*VDn];              // gate g
__device__ float g_bufGC[NROWS*KDn];              // gk then (in place) per-chunk cumsum
__device__ float g_bufT [NROWS*RANKn];            // low-rank intermediate
__device__ float g_bufA [Bsz*NCn*Hn*Csz*Csz];     // intra-chunk attention (masked)
__device__ float g_bufKV[Bsz*Hn*NCn*DKn*DVn];     // per-chunk kv outer products
__device__ float g_bufS [Bsz*Hn*NCn*DKn*DVn];     // state entering each chunk
__device__ float g_bufO [NROWS*VDn];              // attention output (pre-norm)
__device__ float g_bufZ [NROWS*VDn];              // normed+gated, input to final GEMM

__device__ __forceinline__ float* proj_out(int sel){
    switch(sel){
        case 0: return g_bufQ;
        case 1: return g_bufK;
        case 2: return g_bufV;
        default: return g_bufG;
    }
}

// ---------------- generic fp32 tiled GEMM: C[M,N] = alpha * A[M,K] @ B[K,N] ----
// 64x64 block tile, 16 K-step, 256 threads, 4x4 per thread. All dims multiples.
__device__ __forceinline__ void gemm_body(const float* __restrict__ A,
                                          const float* __restrict__ Bm,
                                          float* __restrict__ C,
                                          int N, int K, float alpha)
{
    __shared__ float sA[16][65];
    __shared__ float sB[16][65];
    const int bm = blockIdx.y * 64;
    const int bn = blockIdx.x * 64;
    const int tid = threadIdx.x;
    const int ty = tid >> 4, tx = tid & 15;
    float acc[4][4] = {};

    for (int k0 = 0; k0 < K; k0 += 16){
        #pragma unroll
        for (int rep = 0; rep < 4; rep++){
            int i = tid + rep*256;
            int r = i >> 4, c = i & 15;
            sA[c][r] = A[(size_t)(bm + r) * K + k0 + c];
        }
        #pragma unroll
        for (int rep = 0; rep < 4; rep++){
            int i = tid + rep*256;
            int r = i >> 6, c = i & 63;
            sB[r][c] = Bm[(size_t)(k0 + r) * N + bn + c];
        }
        __syncthreads();
        #pragma unroll
        for (int kk = 0; kk < 16; kk++){
            float a[4], b[4];
            #pragma unroll
            for (int u = 0; u < 4; u++){ a[u] = sA[kk][ty*4+u]; b[u] = sB[kk][tx*4+u]; }
            #pragma unroll
            for (int u = 0; u < 4; u++)
                #pragma unroll
                for (int w = 0; w < 4; w++)
                    acc[u][w] += a[u] * b[w];
        }
        __syncthreads();
    }
    #pragma unroll
    for (int u = 0; u < 4; u++)
        #pragma unroll
        for (int w = 0; w < 4; w++)
            C[(size_t)(bm + ty*4 + u) * N + bn + tx*4 + w] = alpha * acc[u][w];
}

__global__ void gemm_proj_kernel(const float* __restrict__ x,
                                 const float* __restrict__ W,
                                 int sel, int N, float alpha)
{
    gemm_body(x, W, proj_out(sel), N, Dsz, alpha);
}

__global__ void gemm_final_kernel(const float* __restrict__ Wo,
                                  float* __restrict__ out)
{
    gemm_body(g_bufZ, Wo, out, Dsz, VDn, 1.0f);
}

// ---------------- t = x @ Wgk1  ([8192,1024] @ [1024,16]) ----------------------
__global__ void gemm_t_kernel(const float* __restrict__ x,
                              const float* __restrict__ W)
{
    __shared__ float sA[16][65];
    __shared__ float sB[16][17];
    const int bm = blockIdx.x * 64;
    const int tid = threadIdx.x;
    const int ty = tid >> 4, tx = tid & 15;
    float acc[4] = {};
    for (int k0 = 0; k0 < Dsz; k0 += 16){
        #pragma unroll
        for (int rep = 0; rep < 4; rep++){
            int i = tid + rep*256;
            int r = i >> 4, c = i & 15;
            sA[c][r] = x[(size_t)(bm + r) * Dsz + k0 + c];
        }
        { // 16x16 weight tile
            int r = tid >> 4, c = tid & 15;
            sB[r][c] = W[(size_t)(k0 + r) * RANKn + c];
        }
        __syncthreads();
        #pragma unroll
        for (int kk = 0; kk < 16; kk++){
            float b = sB[kk][tx];
            #pragma unroll
            for (int u = 0; u < 4; u++)
                acc[u] += sA[kk][ty*4+u] * b;
        }
        __syncthreads();
    }
    #pragma unroll
    for (int u = 0; u < 4; u++)
        g_bufT[(size_t)(bm + ty*4 + u) * RANKn + tx] = acc[u];
}

// ---------------- gk = log_sigmoid(t @ Wgk2 + bgk) / 16 -----------------------
__global__ void gk_kernel(const float* __restrict__ Wgk2,
                          const float* __restrict__ bgk)
{
    const int col = blockIdx.x * 256 + threadIdx.x;   // 0..511
    const int row = blockIdx.y;
    __shared__ float st[RANKn];
    if (threadIdx.x < RANKn) st[threadIdx.x] = g_bufT[(size_t)row * RANKn + threadIdx.x];
    __syncthreads();
    float acc = bgk[col];
    #pragma unroll
    for (int r = 0; r < RANKn; r++)
        acc += st[r] * Wgk2[r * KDn + col];
    float ls = fminf(acc, 0.0f) - log1pf(expf(-fabsf(acc)));   // stable log_sigmoid
    g_bufGC[(size_t)row * KDn + col] = ls * (1.0f / 16.0f);
}

// ---------------- per-chunk cumsum of gk along time (in place) ----------------
__global__ void gcum_kernel()
{
    const int ch    = blockIdx.y * 256 + threadIdx.x;  // channel 0..511
    const int chunk = blockIdx.x;                      // 0..127 (b*NC+n)
    const int row0  = chunk * Csz;
    float s = 0.0f;
    for (int t = 0; t < Csz; t++){
        size_t idx = (size_t)(row0 + t) * KDn + ch;
        s += g_bufGC[idx];
        g_bufGC[idx] = s;
    }
}

// ---------------- intra-chunk A = tril( (q*e^g) @ (k*e^-g)^T ) -----------------
__global__ void attnA_kernel()
{
    const int chunk = blockIdx.x;        // 0..127
    const int h     = blockIdx.y;        // 0..3
    const int row0  = chunk * Csz;
    const int cb    = h * DKn;
    const int tid = threadIdx.x;
    const int ty = tid >> 4, tx = tid & 15;
    __shared__ float sq[16][65];
    __shared__ float sk[16][65];
    float acc[4][4] = {};
    for (int k0 = 0; k0 < DKn; k0 += 16){
        #pragma unroll
        for (int rep = 0; rep < 4; rep++){
            int i = tid + rep*256;
            int t = i >> 4, kk = i & 15;
            size_t idx = (size_t)(row0 + t) * KDn + cb + k0 + kk;
            float g = g_bufGC[idx];
            sq[kk][t] = g_bufQ[idx] * expf(g);
            sk[kk][t] = g_bufK[idx] * expf(-g);
        }
        __syncthreads();
        #pragma unroll
        for (int kk = 0; kk < 16; kk++){
            float a[4], b[4];
            #pragma unroll
            for (int u = 0; u < 4; u++){ a[u] = sq[kk][ty*4+u]; b[u] = sk[kk][tx*4+u]; }
            #pragma unroll
            for (int u = 0; u < 4; u++)
                #pragma unroll
                for (int w = 0; w < 4; w++)
                    acc[u][w] += a[u] * b[w];
        }
        __syncthreads();
    }
    #pragma unroll
    for (int u = 0; u < 4; u++)
        #pragma unroll
        for (int w = 0; w < 4; w++){
            int t = ty*4 + u, s = tx*4 + w;
            g_bufA[((size_t)(chunk*Hn + h) * Csz + t) * Csz + s] = (t >= s) ? acc[u][w] : 0.0f;
        }
}

// ---------------- per-chunk kv[k,v] = sum_s k_dec[s,k] * v[s,v] ----------------
__global__ void kv_kernel()
{
    const int chunk = blockIdx.x;         // 0..127
    const int h     = blockIdx.y;         // 0..3
    const int vb    = blockIdx.z;         // 0..3 (64 v-cols each)
    const int row0  = chunk * Csz;
    const int kc    = h * DKn;
    const int vc0   = h * DVn + vb * 64;
    const int n     = chunk & 63;
    const int bh    = (chunk >> 6) * Hn + h;
    const int tid = threadIdx.x;
    const int ty = tid >> 4, tx = tid & 15;

    __shared__ float skd[16][128];
    __shared__ float sv [16][65];
    __shared__ float gl [DKn];
    if (tid < DKn) gl[tid] = g_bufGC[(size_t)(row0 + Csz - 1) * KDn + kc + tid];
    __syncthreads();

    float acc[8][4] = {};
    for (int s0 = 0; s0 < Csz; s0 += 16){
        #pragma unroll
        for (int rep = 0; rep < 8; rep++){
            int i = tid + rep*256;
            int ss = i >> 7, kk = i & 127;
            size_t idx = (size_t)(row0 + s0 + ss) * KDn + kc + kk;
            skd[ss][kk] = g_bufK[idx] * expf(gl[kk] - g_bufGC[idx]);
        }
        #pragma unroll
        for (int rep = 0; rep < 4; rep++){
            int i = tid + rep*256;
            int ss = i >> 6, vv = i & 63;
            sv[ss][vv] = g_bufV[(size_t)(row0 + s0 + ss) * VDn + vc0 + vv];
        }
        __syncthreads();
        #pragma unroll
        for (int ss = 0; ss < 16; ss++){
            float a[8], b[4];
            #pragma unroll
            for (int u = 0; u < 8; u++) a[u] = skd[ss][ty*8+u];
            #pragma unroll
            for (int w = 0; w < 4; w++) b[w] = sv[ss][tx*4+w];
            #pragma unroll
            for (int u = 0; u < 8; u++)
                #pragma unroll
                for (int w = 0; w < 4; w++)
                    acc[u][w] += a[u] * b[w];
        }
        __syncthreads();
    }
    size_t base = ((size_t)(bh * NCn + n)) * DKn * DVn;
    #pragma unroll
    for (int u = 0; u < 8; u++)
        #pragma unroll
        for (int w = 0; w < 4; w++)
            g_bufKV[base + (size_t)(ty*8+u) * DVn + vb*64 + tx*4 + w] = acc[u][w];
}

// ---------------- inter-chunk scan: S_0=0; S_{n+1}=S_n*e^{gl_n}+kv_n ------------
__global__ void scan_kernel()
{
    const int bh   = blockIdx.x;                       // 0..7
    const int elem = blockIdx.y * 256 + threadIdx.x;   // 0..32767
    const int kk   = elem >> 8;                        // /256
    const int b    = bh / Hn, h = bh % Hn;
    float s = 0.0f;
    for (int n = 0; n < NCn; n++){
        size_t base = ((size_t)(bh * NCn + n)) * (DKn * DVn);
        g_bufS[base + elem] = s;
        float gl = g_bufGC[(size_t)((b * NCn + n) * Csz + Csz - 1) * KDn + h * DKn + kk];
        s = s * expf(gl) + g_bufKV[base + elem];
    }
}

// ---------------- o = A @ v_chunk + q_t @ S_n ----------------------------------
__global__ void out_kernel()
{
    const int chunk = blockIdx.x;         // 0..127
    const int h     = blockIdx.y;         // 0..3
    const int vb    = blockIdx.z;         // 0..3
    const int row0  = chunk * Csz;
    const int n     = chunk & 63;
    const int bh    = (chunk >> 6) * Hn + h;
    const int vcol  = h * DVn + vb * 64;
    const int tid = threadIdx.x;
    const int ty = tid >> 4, tx = tid & 15;

    __shared__ float sa[16][65];
    __shared__ float sb[16][65];
    float acc[4][4] = {};

    // intra: A[64,64] @ v[64,64]
    for (int s0 = 0; s0 < Csz; s0 += 16){
        #pragma unroll
        for (int rep = 0; rep < 4; rep++){
            int i = tid + rep*256;
            int t = i >> 4, ss = i & 15;
            sa[ss][t] = g_bufA[((size_t)(chunk*Hn + h) * Csz + t) * Csz + s0 + ss];
        }
        #pragma unroll
        for (int rep = 0; rep < 4; rep++){
            int i = tid + rep*256;
            int ss = i >> 6, vv = i & 63;
            sb[ss][vv] = g_bufV[(size_t)(row0 + s0 + ss) * VDn + vcol + vv];
        }
        __syncthreads();
        #pragma unroll
        for (int ss = 0; ss < 16; ss++){
            float a[4], b[4];
            #pragma unroll
            for (int u = 0; u < 4; u++){ a[u] = sa[ss][ty*4+u]; b[u] = sb[ss][tx*4+u]; }
            #pragma unroll
            for (int u = 0; u < 4; u++)
                #pragma unroll
                for (int w = 0; w < 4; w++)
                    acc[u][w] += a[u] * b[w];
        }
        __syncthreads();
    }

    // inter: q_t[64,128] @ S[128,64]
    const size_t sbase = ((size_t)(bh * NCn + n)) * (DKn * DVn);
    for (int k0 = 0; k0 < DKn; k0 += 16){
        #pragma unroll
        for (int rep = 0; rep < 4; rep++){
            int i = tid + rep*256;
            int t = i >> 4, kk = i & 15;
            size_t idx = (size_t)(row0 + t) * KDn + h * DKn + k0 + kk;
            sa[kk][t] = g_bufQ[idx] * expf(g_bufGC[idx]);
        }
        #pragma unroll
        for (int rep = 0; rep < 4; rep++){
            int i = tid + rep*256;
            int kk = i >> 6, vv = i & 63;
            sb[kk][vv] = g_bufS[sbase + (size_t)(k0 + kk) * DVn + vb*64 + vv];
        }
        __syncthreads();
        #pragma unroll
        for (int kk = 0; kk < 16; kk++){
            float a[4], b[4];
            #pragma unroll
            for (int u = 0; u < 4; u++){ a[u] = sa[kk][ty*4+u]; b[u] = sb[kk][tx*4+u]; }
            #pragma unroll
            for (int u = 0; u < 4; u++)
                #pragma unroll
                for (int w = 0; w < 4; w++)
                    acc[u][w] += a[u] * b[w];
        }
        __syncthreads();
    }

    #pragma unroll
    for (int u = 0; u < 4; u++)
        #pragma unroll
        for (int w = 0; w < 4; w++)
            g_bufO[(size_t)(row0 + ty*4 + u) * VDn + vcol + tx*4 + w] = acc[u][w];
}

// ---------------- RMS-norm over DV + SiLU gate ---------------------------------
// NOTE: norm_w has shape (DV,) = (256,) — shared across heads.
__global__ void norm_gate_kernel(const float* __restrict__ norm_w)
{
    const int row = blockIdx.x;
    const int h   = blockIdx.y;
    const int tid = threadIdx.x;   // 256 == DVn
    size_t idx = (size_t)row * VDn + h * DVn + tid;
    float o = g_bufO[idx];
    float sq = o * o;
    #pragma unroll
    for (int off = 16; off; off >>= 1) sq += __shfl_xor_sync(0xffffffffu, sq, off);
    __shared__ float ws[8];
    if ((tid & 31) == 0) ws[tid >> 5] = sq;
    __syncthreads();
    float tot = 0.0f;
    #pragma unroll
    for (int i = 0; i < 8; i++) tot += ws[i];
    float r = rsqrtf(tot * (1.0f / 256.0f) + 1e-5f);
    float gv = g_bufG[idx];
    float silu = gv / (1.0f + expf(-gv));
    g_bufZ[idx] = o * r * norm_w[tid] * silu;
}

// ---------------- launcher ------------------------------------------------------
extern "C" void kernel_launch(void* const* d_in, const int* in_sizes, int n_in,
                              void* d_out, int out_size)
{
    const float* x     = (const float*)d_in[0];
    const float* Wq    = (const float*)d_in[1];
    const float* Wk    = (const float*)d_in[2];
    const float* Wv    = (const float*)d_in[3];
    const float* Wgk1  = (const float*)d_in[4];
    const float* Wgk2  = (const float*)d_in[5];
    const float* bgk   = (const float*)d_in[6];
    const float* Wg    = (const float*)d_in[7];
    const float* Wo    = (const float*)d_in[8];
    const float* normw = (const float*)d_in[9];
    float* out = (float*)d_out;

    const float scale = 0.08838834764831845f;   // DK^-0.5 = 1/sqrt(128)
    dim3 blk(256);

    // projections
    gemm_proj_kernel<<<dim3(KDn/64, NROWS/64), blk>>>(x, Wq, 0, KDn, scale);
    gemm_proj_kernel<<<dim3(KDn/64, NROWS/64), blk>>>(x, Wk, 1, KDn, 1.0f);
    gemm_proj_kernel<<<dim3(VDn/64, NROWS/64), blk>>>(x, Wv, 2, VDn, 1.0f);
    gemm_proj_kernel<<<dim3(VDn/64, NROWS/64), blk>>>(x, Wg, 3, VDn, 1.0f);

    // low-rank gate path
    gemm_t_kernel<<<NROWS/64, blk>>>(x, Wgk1);
    gk_kernel<<<dim3(KDn/256, NROWS), blk>>>(Wgk2, bgk);
    gcum_kernel<<<dim3(Bsz*NCn, KDn/256), blk>>>();

    // GLA chunks
    attnA_kernel<<<dim3(Bsz*NCn, Hn), blk>>>();
    kv_kernel<<<dim3(Bsz*NCn, Hn, DVn/64), blk>>>();
    scan_kernel<<<dim3(Bsz*Hn, (DKn*DVn)/256), blk>>>();
    out_kernel<<<dim3(Bsz*NCn, Hn, DVn/64), blk>>>();

    // epilogue
    norm_gate_kernel<<<dim3(NROWS, Hn), blk>>>(normw);
    gemm_final_kernel<<<dim3(Dsz/64, NROWS/64), blk>>>(Wo, out);
}

// round 4
// speedup vs baseline: 2.8494x; 2.8481x over previous
#include <cuda_runtime.h>
#include <math.h>

// Problem constants
#define Bsz   2
#define Ssz   4096
#define Dsz   1024
#define Hn    4
#define DKn   128
#define DVn   256
#define KDn   512     // H*DK
#define VDn   1024    // H*DV
#define Csz   64
#define NCn   64      // S / C
#define RANKn 16
#define NROWS (Bsz*Ssz)   // 8192

// ---------------- scratch (device globals; no allocation allowed) -------------
__device__ float g_bufQ [NROWS*KDn];
__device__ float g_bufK [NROWS*KDn];
__device__ float g_bufV [NROWS*VDn];
__device__ float g_bufG [NROWS*VDn];
__device__ float g_bufGC[NROWS*KDn];
__device__ float g_bufT [NROWS*RANKn];
__device__ float g_bufA [Bsz*NCn*Hn*Csz*Csz];
__device__ float g_bufKV[Bsz*Hn*NCn*DKn*DVn];
__device__ float g_bufS [Bsz*Hn*NCn*DKn*DVn];
__device__ float g_bufO [NROWS*VDn];
__device__ float g_bufZ [NROWS*VDn];

__device__ __forceinline__ float* proj_out(int sel){
    switch(sel){
        case 0: return g_bufQ;
        case 1: return g_bufK;
        case 2: return g_bufV;
        default: return g_bufG;
    }
}

// ================= TF32 tensor-core GEMM =======================================
// C[M,N] = alpha * A[M,1024] @ B[1024,N].  Block tile 128x128, K-step 32,
// 256 threads = 8 warps, warp tile 64x32 via mma.sync.m16n8k8 (4 m-tiles x 4 n-tiles).

__device__ __forceinline__ unsigned f2tf32(float f){
    unsigned u;
    asm("cvt.rna.tf32.f32 %0, %1;" : "=r"(u) : "f"(f));
    return u;
}

__device__ __forceinline__ void mma_tf32(float* d, const unsigned* a, const unsigned* b){
    asm volatile(
        "mma.sync.aligned.m16n8k8.row.col.f32.tf32.tf32.f32 "
        "{%0,%1,%2,%3}, {%4,%5,%6,%7}, {%8,%9}, {%0,%1,%2,%3};\n"
        : "+f"(d[0]), "+f"(d[1]), "+f"(d[2]), "+f"(d[3])
        : "r"(a[0]), "r"(a[1]), "r"(a[2]), "r"(a[3]), "r"(b[0]), "r"(b[1]));
}

// Padding analysis (fp32 words, 32 banks):
//  sA[128][36]:  a-frag addr = 36*(g + base) + r  -> bank = (4g + r) % 32 = lane. conflict-free.
//  sB[32][136]:  b-frag addr = 136*(ks + r) + col -> bank = (8r + g + c) % 32, r in 0..3 g in 0..7
//                -> {8r+g} covers 0..31 exactly. conflict-free.
__device__ __forceinline__ void tf32_gemm_body(const float* __restrict__ A,
                                               const float* __restrict__ Bm,
                                               float* __restrict__ C,
                                               int N, float alpha)
{
    __shared__ unsigned sA[128][36];
    __shared__ unsigned sB[32][136];

    const int bm = blockIdx.y * 128;
    const int bn = blockIdx.x * 128;
    const int tid  = threadIdx.x;
    const int lane = tid & 31;
    const int wid  = tid >> 5;
    const int wm = (wid >> 2) * 64;     // warp row base (0 or 64)
    const int wn = (wid & 3) * 32;      // warp col base (0,32,64,96)
    const int g = lane >> 2;            // groupID
    const int r = lane & 3;             // threadID_in_group

    float acc[4][4][4];
    #pragma unroll
    for (int mt = 0; mt < 4; mt++)
        #pragma unroll
        for (int nt = 0; nt < 4; nt++)
            #pragma unroll
            for (int i = 0; i < 4; i++) acc[mt][nt][i] = 0.0f;

    #pragma unroll 1
    for (int k0 = 0; k0 < 1024; k0 += 32){
        // ---- load A tile [128 x 32] ----
        #pragma unroll
        for (int rep = 0; rep < 4; rep++){
            int i  = tid + rep * 256;
            int rr = i >> 3;
            int cc = (i & 7) * 4;
            float4 v = *(const float4*)&A[(size_t)(bm + rr) * 1024 + k0 + cc];
            uint4 u;
            u.x = f2tf32(v.x); u.y = f2tf32(v.y); u.z = f2tf32(v.z); u.w = f2tf32(v.w);
            *(uint4*)&sA[rr][cc] = u;
        }
        // ---- load B tile [32 x 128] ----
        #pragma unroll
        for (int rep = 0; rep < 4; rep++){
            int i  = tid + rep * 256;
            int kk = i >> 5;
            int cc = (i & 31) * 4;
            float4 v = *(const float4*)&Bm[(size_t)(k0 + kk) * N + bn + cc];
            uint4 u;
            u.x = f2tf32(v.x); u.y = f2tf32(v.y); u.z = f2tf32(v.z); u.w = f2tf32(v.w);
            *(uint4*)&sB[kk][cc] = u;
        }
        __syncthreads();

        #pragma unroll
        for (int ks = 0; ks < 32; ks += 8){
            unsigned af[4][4], bf[4][2];
            #pragma unroll
            for (int mt = 0; mt < 4; mt++){
                int row0 = wm + 16*mt + g;
                af[mt][0] = sA[row0    ][ks + r    ];
                af[mt][1] = sA[row0 + 8][ks + r    ];
                af[mt][2] = sA[row0    ][ks + r + 4];
                af[mt][3] = sA[row0 + 8][ks + r + 4];
            }
            #pragma unroll
            for (int nt = 0; nt < 4; nt++){
                int col = wn + 8*nt + g;
                bf[nt][0] = sB[ks + r    ][col];
                bf[nt][1] = sB[ks + r + 4][col];
            }
            #pragma unroll
            for (int mt = 0; mt < 4; mt++)
                #pragma unroll
                for (int nt = 0; nt < 4; nt++)
                    mma_tf32(acc[mt][nt], af[mt], bf[nt]);
        }
        __syncthreads();
    }

    // ---- epilogue: c0,c1 -> (row, 2r..2r+1), c2,c3 -> (row+8, ...) ----
    #pragma unroll
    for (int mt = 0; mt < 4; mt++){
        int row = bm + wm + 16*mt + g;
        #pragma unroll
        for (int nt = 0; nt < 4; nt++){
            int col = bn + wn + 8*nt + 2*r;
            float2 v0 = make_float2(alpha*acc[mt][nt][0], alpha*acc[mt][nt][1]);
            float2 v1 = make_float2(alpha*acc[mt][nt][2], alpha*acc[mt][nt][3]);
            *(float2*)&C[(size_t)row       * N + col] = v0;
            *(float2*)&C[(size_t)(row + 8) * N + col] = v1;
        }
    }
}

__global__ void __launch_bounds__(256, 2)
tf32_proj_kernel(const float* __restrict__ x, const float* __restrict__ W,
                 int sel, int N, float alpha)
{
    tf32_gemm_body(x, W, proj_out(sel), N, alpha);
}

__global__ void __launch_bounds__(256, 2)
tf32_final_kernel(const float* __restrict__ Wo, float* __restrict__ out)
{
    tf32_gemm_body(g_bufZ, Wo, out, Dsz, 1.0f);
}

// ---------------- t = x @ Wgk1  ([8192,1024] @ [1024,16]) ----------------------
__global__ void gemm_t_kernel(const float* __restrict__ x,
                              const float* __restrict__ W)
{
    __shared__ float sA[16][65];
    __shared__ float sB[16][17];
    const int bm = blockIdx.x * 64;
    const int tid = threadIdx.x;
    const int ty = tid >> 4, tx = tid & 15;
    float acc[4] = {};
    for (int k0 = 0; k0 < Dsz; k0 += 16){
        #pragma unroll
        for (int rep = 0; rep < 4; rep++){
            int i = tid + rep*256;
            int r = i >> 4, c = i & 15;
            sA[c][r] = x[(size_t)(bm + r) * Dsz + k0 + c];
        }
        {
            int r = tid >> 4, c = tid & 15;
            sB[r][c] = W[(size_t)(k0 + r) * RANKn + c];
        }
        __syncthreads();
        #pragma unroll
        for (int kk = 0; kk < 16; kk++){
            float b = sB[kk][tx];
            #pragma unroll
            for (int u = 0; u < 4; u++)
                acc[u] += sA[kk][ty*4+u] * b;
        }
        __syncthreads();
    }
    #pragma unroll
    for (int u = 0; u < 4; u++)
        g_bufT[(size_t)(bm + ty*4 + u) * RANKn + tx] = acc[u];
}

// ---------------- gk = log_sigmoid(t @ Wgk2 + bgk) / 16 -----------------------
__global__ void gk_kernel(const float* __restrict__ Wgk2,
                          const float* __restrict__ bgk)
{
    const int col = blockIdx.x * 256 + threadIdx.x;
    const int row = blockIdx.y;
    __shared__ float st[RANKn];
    if (threadIdx.x < RANKn) st[threadIdx.x] = g_bufT[(size_t)row * RANKn + threadIdx.x];
    __syncthreads();
    float acc = bgk[col];
    #pragma unroll
    for (int r = 0; r < RANKn; r++)
        acc += st[r] * Wgk2[r * KDn + col];
    float ls = fminf(acc, 0.0f) - log1pf(expf(-fabsf(acc)));
    g_bufGC[(size_t)row * KDn + col] = ls * (1.0f / 16.0f);
}

// ---------------- per-chunk cumsum of gk along time (in place) ----------------
__global__ void gcum_kernel()
{
    const int ch    = blockIdx.y * 256 + threadIdx.x;
    const int chunk = blockIdx.x;
    const int row0  = chunk * Csz;
    float s = 0.0f;
    for (int t = 0; t < Csz; t++){
        size_t idx = (size_t)(row0 + t) * KDn + ch;
        s += g_bufGC[idx];
        g_bufGC[idx] = s;
    }
}

// ---------------- intra-chunk A = tril( (q*e^g) @ (k*e^-g)^T ) -----------------
__global__ void attnA_kernel()
{
    const int chunk = blockIdx.x;
    const int h     = blockIdx.y;
    const int row0  = chunk * Csz;
    const int cb    = h * DKn;
    const int tid = threadIdx.x;
    const int ty = tid >> 4, tx = tid & 15;
    __shared__ float sq[16][65];
    __shared__ float sk[16][65];
    float acc[4][4] = {};
    for (int k0 = 0; k0 < DKn; k0 += 16){
        #pragma unroll
        for (int rep = 0; rep < 4; rep++){
            int i = tid + rep*256;
            int t = i >> 4, kk = i & 15;
            size_t idx = (size_t)(row0 + t) * KDn + cb + k0 + kk;
            float g = g_bufGC[idx];
            sq[kk][t] = g_bufQ[idx] * expf(g);
            sk[kk][t] = g_bufK[idx] * expf(-g);
        }
        __syncthreads();
        #pragma unroll
        for (int kk = 0; kk < 16; kk++){
            float a[4], b[4];
            #pragma unroll
            for (int u = 0; u < 4; u++){ a[u] = sq[kk][ty*4+u]; b[u] = sk[kk][tx*4+u]; }
            #pragma unroll
            for (int u = 0; u < 4; u++)
                #pragma unroll
                for (int w = 0; w < 4; w++)
                    acc[u][w] += a[u] * b[w];
        }
        __syncthreads();
    }
    #pragma unroll
    for (int u = 0; u < 4; u++)
        #pragma unroll
        for (int w = 0; w < 4; w++){
            int t = ty*4 + u, s = tx*4 + w;
            g_bufA[((size_t)(chunk*Hn + h) * Csz + t) * Csz + s] = (t >= s) ? acc[u][w] : 0.0f;
        }
}

// ---------------- per-chunk kv[k,v] = sum_s k_dec[s,k] * v[s,v] ----------------
__global__ void kv_kernel()
{
    const int chunk = blockIdx.x;
    const int h     = blockIdx.y;
    const int vb    = blockIdx.z;
    const int row0  = chunk * Csz;
    const int kc    = h * DKn;
    const int vc0   = h * DVn + vb * 64;
    const int n     = chunk & 63;
    const int bh    = (chunk >> 6) * Hn + h;
    const int tid = threadIdx.x;
    const int ty = tid >> 4, tx = tid & 15;

    __shared__ float skd[16][128];
    __shared__ float sv [16][65];
    __shared__ float gl [DKn];
    if (tid < DKn) gl[tid] = g_bufGC[(size_t)(row0 + Csz - 1) * KDn + kc + tid];
    __syncthreads();

    float acc[8][4] = {};
    for (int s0 = 0; s0 < Csz; s0 += 16){
        #pragma unroll
        for (int rep = 0; rep < 8; rep++){
            int i = tid + rep*256;
            int ss = i >> 7, kk = i & 127;
            size_t idx = (size_t)(row0 + s0 + ss) * KDn + kc + kk;
            skd[ss][kk] = g_bufK[idx] * expf(gl[kk] - g_bufGC[idx]);
        }
        #pragma unroll
        for (int rep = 0; rep < 4; rep++){
            int i = tid + rep*256;
            int ss = i >> 6, vv = i & 63;
            sv[ss][vv] = g_bufV[(size_t)(row0 + s0 + ss) * VDn + vc0 + vv];
        }
        __syncthreads();
        #pragma unroll
        for (int ss = 0; ss < 16; ss++){
            float a[8], b[4];
            #pragma unroll
            for (int u = 0; u < 8; u++) a[u] = skd[ss][ty*8+u];
            #pragma unroll
            for (int w = 0; w < 4; w++) b[w] = sv[ss][tx*4+w];
            #pragma unroll
            for (int u = 0; u < 8; u++)
                #pragma unroll
                for (int w = 0; w < 4; w++)
                    acc[u][w] += a[u] * b[w];
        }
        __syncthreads();
    }
    size_t base = ((size_t)(bh * NCn + n)) * DKn * DVn;
    #pragma unroll
    for (int u = 0; u < 8; u++)
        #pragma unroll
        for (int w = 0; w < 4; w++)
            g_bufKV[base + (size_t)(ty*8+u) * DVn + vb*64 + tx*4 + w] = acc[u][w];
}

// ---------------- inter-chunk scan: S_0=0; S_{n+1}=S_n*e^{gl_n}+kv_n ------------
__global__ void scan_kernel()
{
    const int bh   = blockIdx.x;
    const int elem = blockIdx.y * 256 + threadIdx.x;
    const int kk   = elem >> 8;
    const int b    = bh / Hn, h = bh % Hn;
    float s = 0.0f;
    for (int n = 0; n < NCn; n++){
        size_t base = ((size_t)(bh * NCn + n)) * (DKn * DVn);
        g_bufS[base + elem] = s;
        float gl = g_bufGC[(size_t)((b * NCn + n) * Csz + Csz - 1) * KDn + h * DKn + kk];
        s = s * expf(gl) + g_bufKV[base + elem];
    }
}

// ---------------- o = A @ v_chunk + q_t @ S_n ----------------------------------
__global__ void out_kernel()
{
    const int chunk = blockIdx.x;
    const int h     = blockIdx.y;
    const int vb    = blockIdx.z;
    const int row0  = chunk * Csz;
    const int n     = chunk & 63;
    const int bh    = (chunk >> 6) * Hn + h;
    const int vcol  = h * DVn + vb * 64;
    const int tid = threadIdx.x;
    const int ty = tid >> 4, tx = tid & 15;

    __shared__ float sa[16][65];
    __shared__ float sb[16][65];
    float acc[4][4] = {};

    for (int s0 = 0; s0 < Csz; s0 += 16){
        #pragma unroll
        for (int rep = 0; rep < 4; rep++){
            int i = tid + rep*256;
            int t = i >> 4, ss = i & 15;
            sa[ss][t] = g_bufA[((size_t)(chunk*Hn + h) * Csz + t) * Csz + s0 + ss];
        }
        #pragma unroll
        for (int rep = 0; rep < 4; rep++){
            int i = tid + rep*256;
            int ss = i >> 6, vv = i & 63;
            sb[ss][vv] = g_bufV[(size_t)(row0 + s0 + ss) * VDn + vcol + vv];
        }
        __syncthreads();
        #pragma unroll
        for (int ss = 0; ss < 16; ss++){
            float a[4], b[4];
            #pragma unroll
            for (int u = 0; u < 4; u++){ a[u] = sa[ss][ty*4+u]; b[u] = sb[ss][tx*4+u]; }
            #pragma unroll
            for (int u = 0; u < 4; u++)
                #pragma unroll
                for (int w = 0; w < 4; w++)
                    acc[u][w] += a[u] * b[w];
        }
        __syncthreads();
    }

    const size_t sbase = ((size_t)(bh * NCn + n)) * (DKn * DVn);
    for (int k0 = 0; k0 < DKn; k0 += 16){
        #pragma unroll
        for (int rep = 0; rep < 4; rep++){
            int i = tid + rep*256;
            int t = i >> 4, kk = i & 15;
            size_t idx = (size_t)(row0 + t) * KDn + h * DKn + k0 + kk;
            sa[kk][t] = g_bufQ[idx] * expf(g_bufGC[idx]);
        }
        #pragma unroll
        for (int rep = 0; rep < 4; rep++){
            int i = tid + rep*256;
            int kk = i >> 6, vv = i & 63;
            sb[kk][vv] = g_bufS[sbase + (size_t)(k0 + kk) * DVn + vb*64 + vv];
        }
        __syncthreads();
        #pragma unroll
        for (int kk = 0; kk < 16; kk++){
            float a[4], b[4];
            #pragma unroll
            for (int u = 0; u < 4; u++){ a[u] = sa[kk][ty*4+u]; b[u] = sb[kk][tx*4+u]; }
            #pragma unroll
            for (int u = 0; u < 4; u++)
                #pragma unroll
                for (int w = 0; w < 4; w++)
                    acc[u][w] += a[u] * b[w];
        }
        __syncthreads();
    }

    #pragma unroll
    for (int u = 0; u < 4; u++)
        #pragma unroll
        for (int w = 0; w < 4; w++)
            g_bufO[(size_t)(row0 + ty*4 + u) * VDn + vcol + tx*4 + w] = acc[u][w];
}

// ---------------- RMS-norm over DV + SiLU gate (norm_w shape (DV,)) ------------
__global__ void norm_gate_kernel(const float* __restrict__ norm_w)
{
    const int row = blockIdx.x;
    const int h   = blockIdx.y;
    const int tid = threadIdx.x;   // 256 == DVn
    size_t idx = (size_t)row * VDn + h * DVn + tid;
    float o = g_bufO[idx];
    float sq = o * o;
    #pragma unroll
    for (int off = 16; off; off >>= 1) sq += __shfl_xor_sync(0xffffffffu, sq, off);
    __shared__ float ws[8];
    if ((tid & 31) == 0) ws[tid >> 5] = sq;
    __syncthreads();
    float tot = 0.0f;
    #pragma unroll
    for (int i = 0; i < 8; i++) tot += ws[i];
    float r = rsqrtf(tot * (1.0f / 256.0f) + 1e-5f);
    float gv = g_bufG[idx];
    float silu = gv / (1.0f + expf(-gv));
    g_bufZ[idx] = o * r * norm_w[tid] * silu;
}

// ---------------- launcher ------------------------------------------------------
extern "C" void kernel_launch(void* const* d_in, const int* in_sizes, int n_in,
                              void* d_out, int out_size)
{
    const float* x     = (const float*)d_in[0];
    const float* Wq    = (const float*)d_in[1];
    const float* Wk    = (const float*)d_in[2];
    const float* Wv    = (const float*)d_in[3];
    const float* Wgk1  = (const float*)d_in[4];
    const float* Wgk2  = (const float*)d_in[5];
    const float* bgk   = (const float*)d_in[6];
    const float* Wg    = (const float*)d_in[7];
    const float* Wo    = (const float*)d_in[8];
    const float* normw = (const float*)d_in[9];
    float* out = (float*)d_out;

    const float scale = 0.08838834764831845f;   // 1/sqrt(128)
    dim3 blk(256);

    // projections on the tensor pipe (TF32)
    tf32_proj_kernel<<<dim3(KDn/128, NROWS/128), blk>>>(x, Wq, 0, KDn, scale);
    tf32_proj_kernel<<<dim3(KDn/128, NROWS/128), blk>>>(x, Wk, 1, KDn, 1.0f);
    tf32_proj_kernel<<<dim3(VDn*Hn/128/4, NROWS/128), dim3(256)>>>(x, Wv, 2, VDn, 1.0f);
    tf32_proj_kernel<<<dim3(VDn*Hn/128/4, NROWS/128), dim3(256)>>>(x, Wg, 3, VDn, 1.0f);

    // low-rank gate path
    gemm_t_kernel<<<NROWS/64, blk>>>(x, Wgk1);
    gk_kernel<<<dim3(KDn/256, NROWS), blk>>>(Wgk2, bgk);
    gcum_kernel<<<dim3(Bsz*NCn, KDn/256), blk>>>();

    // GLA chunks
    attnA_kernel<<<dim3(Bsz*NCn, Hn), blk>>>();
    kv_kernel<<<dim3(Bsz*NCn, Hn, DVn/64), blk>>>();
    scan_kernel<<<dim3(Bsz*Hn, (DKn*DVn)/256), blk>>>();
    out_kernel<<<dim3(Bsz*NCn, Hn, DVn/64), blk>>>();

    // epilogue
    norm_gate_kernel<<<dim3(NROWS, Hn), blk>>>(normw);
    tf32_final_kernel<<<dim3(Dsz/128, NROWS/128), blk>>>(Wo, out);
}

// round 5
// speedup vs baseline: 2.9807x; 1.0461x over previous
#include <cuda_runtime.h>
#include <math.h>

// Problem constants
#define Bsz   2
#define Ssz   4096
#define Dsz   1024
#define Hn    4
#define DKn   128
#define DVn   256
#define KDn   512     // H*DK
#define VDn   1024    // H*DV
#define Csz   64
#define NCn   64      // S / C
#define RANKn 16
#define NROWS (Bsz*Ssz)   // 8192

// ---------------- scratch (device globals; no allocation allowed) -------------
__device__ float g_bufQ [NROWS*KDn];
__device__ float g_bufK [NROWS*KDn];
__device__ float g_bufV [NROWS*VDn];
__device__ float g_bufG [NROWS*VDn];
__device__ float g_bufGC[NROWS*KDn];
__device__ float g_bufT [NROWS*RANKn];
__device__ float g_bufA [Bsz*NCn*Hn*Csz*Csz];
__device__ float g_bufKV[Bsz*Hn*NCn*DKn*DVn];
__device__ float g_bufS [Bsz*Hn*NCn*DKn*DVn];
__device__ float g_bufO [NROWS*VDn];
__device__ float g_bufZ [NROWS*VDn];

__device__ __forceinline__ float* proj_out(int sel){
    switch(sel){
        case 0: return g_bufQ;
        case 1: return g_bufK;
        case 2: return g_bufV;
        default: return g_bufG;
    }
}

// ================= TF32 tensor-core GEMM (cp.async double-buffered) ============
// C[M,N] = alpha * A[M,1024] @ B[1024,N].  Block tile 128x128, K-step 32,
// 256 threads = 8 warps, warp tile 64x32 via mma.sync.m16n8k8.

__device__ __forceinline__ unsigned f2tf32(float f){
    unsigned u;
    asm("cvt.rna.tf32.f32 %0, %1;" : "=r"(u) : "f"(f));
    return u;
}

__device__ __forceinline__ void mma_tf32(float* d, const unsigned* a, const unsigned* b){
    asm volatile(
        "mma.sync.aligned.m16n8k8.row.col.f32.tf32.tf32.f32 "
        "{%0,%1,%2,%3}, {%4,%5,%6,%7}, {%8,%9}, {%0,%1,%2,%3};\n"
        : "+f"(d[0]), "+f"(d[1]), "+f"(d[2]), "+f"(d[3])
        : "r"(a[0]), "r"(a[1]), "r"(a[2]), "r"(a[3]), "r"(b[0]), "r"(b[1]));
}

__device__ __forceinline__ void cp_async16(void* smem_dst, const void* gmem_src){
    unsigned sa = (unsigned)__cvta_generic_to_shared(smem_dst);
    asm volatile("cp.async.cg.shared.global [%0], [%1], 16;\n" :: "r"(sa), "l"(gmem_src));
}
#define CP_COMMIT()  asm volatile("cp.async.commit_group;\n")
#define CP_WAIT(N)   asm volatile("cp.async.wait_group %0;\n" :: "n"(N))

// SMEM layout (dynamic): sA[2][128][36] floats, then sB[2][32][136] floats.
// Padding: A-frag bank = (4g + r) % 32 = lane (conflict-free);
//          B-frag bank = (8r + g + c) % 32 covers all 32 (conflict-free).
#define SA_STRIDE 36
#define SB_STRIDE 136
#define SA_BUF    (128*SA_STRIDE)
#define SB_BUF    (32*SB_STRIDE)
#define SMEM_FLOATS (2*SA_BUF + 2*SB_BUF)

__device__ __forceinline__ void tf32_load_tiles(float* sA, float* sB,
                                                const float* __restrict__ A,
                                                const float* __restrict__ Bm,
                                                int bm, int bn, int N, int k0, int buf,
                                                int tid)
{
    float* a0 = sA + buf * SA_BUF;
    float* b0 = sB + buf * SB_BUF;
    #pragma unroll
    for (int rep = 0; rep < 4; rep++){
        int i  = tid + rep * 256;
        int rr = i >> 3;
        int cc = (i & 7) * 4;
        cp_async16(&a0[rr * SA_STRIDE + cc], &A[(size_t)(bm + rr) * 1024 + k0 + cc]);
    }
    #pragma unroll
    for (int rep = 0; rep < 4; rep++){
        int i  = tid + rep * 256;
        int kk = i >> 5;
        int cc = (i & 31) * 4;
        cp_async16(&b0[kk * SB_STRIDE + cc], &Bm[(size_t)(k0 + kk) * N + bn + cc]);
    }
    CP_COMMIT();
}

__device__ __forceinline__ void tf32_gemm_body(const float* __restrict__ A,
                                               const float* __restrict__ Bm,
                                               float* __restrict__ C,
                                               int N, float alpha)
{
    extern __shared__ float smem[];
    float* sA = smem;
    float* sB = smem + 2 * SA_BUF;

    const int bm = blockIdx.y * 128;
    const int bn = blockIdx.x * 128;
    const int tid  = threadIdx.x;
    const int lane = tid & 31;
    const int wid  = tid >> 5;
    const int wm = (wid >> 2) * 64;
    const int wn = (wid & 3) * 32;
    const int g = lane >> 2;
    const int r = lane & 3;

    float acc[4][4][4];
    #pragma unroll
    for (int mt = 0; mt < 4; mt++)
        #pragma unroll
        for (int nt = 0; nt < 4; nt++)
            #pragma unroll
            for (int i = 0; i < 4; i++) acc[mt][nt][i] = 0.0f;

    const int NT = 1024 / 32;
    tf32_load_tiles(sA, sB, A, Bm, bm, bn, N, 0, 0, tid);

    #pragma unroll 1
    for (int t = 0; t < NT; t++){
        if (t + 1 < NT)
            tf32_load_tiles(sA, sB, A, Bm, bm, bn, N, (t+1)*32, (t+1)&1, tid);
        if (t + 1 < NT) { CP_WAIT(1); } else { CP_WAIT(0); }
        __syncthreads();

        const float* a0 = sA + (t & 1) * SA_BUF;
        const float* b0 = sB + (t & 1) * SB_BUF;

        #pragma unroll
        for (int ks = 0; ks < 32; ks += 8){
            unsigned af[4][4], bf[4][2];
            #pragma unroll
            for (int mt = 0; mt < 4; mt++){
                int row0 = wm + 16*mt + g;
                af[mt][0] = f2tf32(a0[ row0      * SA_STRIDE + ks + r    ]);
                af[mt][1] = f2tf32(a0[(row0 + 8) * SA_STRIDE + ks + r    ]);
                af[mt][2] = f2tf32(a0[ row0      * SA_STRIDE + ks + r + 4]);
                af[mt][3] = f2tf32(a0[(row0 + 8) * SA_STRIDE + ks + r + 4]);
            }
            #pragma unroll
            for (int nt = 0; nt < 4; nt++){
                int col = wn + 8*nt + g;
                bf[nt][0] = f2tf32(b0[(ks + r    ) * SB_STRIDE + col]);
                bf[nt][1] = f2tf32(b0[(ks + r + 4) * SB_STRIDE + col]);
            }
            #pragma unroll
            for (int mt = 0; mt < 4; mt++)
                #pragma unroll
                for (int nt = 0; nt < 4; nt++)
                    mma_tf32(acc[mt][nt], af[mt], bf[nt]);
        }
        __syncthreads();
    }

    #pragma unroll
    for (int mt = 0; mt < 4; mt++){
        int row = bm + wm + 16*mt + g;
        #pragma unroll
        for (int nt = 0; nt < 4; nt++){
            int col = bn + wn + 8*nt + 2*r;
            float2 v0 = make_float2(alpha*acc[mt][nt][0], alpha*acc[mt][nt][1]);
            float2 v1 = make_float2(alpha*acc[mt][nt][2], alpha*acc[mt][nt][3]);
            *(float2*)&C[(size_t)row       * N + col] = v0;
            *(float2*)&C[(size_t)(row + 8) * N + col] = v1;
        }
    }
}

__global__ void __launch_bounds__(256, 2)
tf32_proj_kernel(const float* __restrict__ x, const float* __restrict__ W,
                 int sel, int N, float alpha)
{
    tf32_gemm_body(x, W, proj_out(sel), N, alpha);
}

__global__ void __launch_bounds__(256, 2)
tf32_final_kernel(const float* __restrict__ Wo, float* __restrict__ out)
{
    tf32_gemm_body(g_bufZ, Wo, out, Dsz, 1.0f);
}

// ---------------- t = x @ Wgk1  ([8192,1024] @ [1024,16]) ----------------------
__global__ void gemm_t_kernel(const float* __restrict__ x,
                              const float* __restrict__ W)
{
    __shared__ float sA[16][65];
    __shared__ float sB[16][17];
    const int bm = blockIdx.x * 64;
    const int tid = threadIdx.x;
    const int ty = tid >> 4, tx = tid & 15;
    float acc[4] = {};
    for (int k0 = 0; k0 < Dsz; k0 += 16){
        #pragma unroll
        for (int rep = 0; rep < 4; rep++){
            int i = tid + rep*256;
            int r = i >> 4, c = i & 15;
            sA[c][r] = x[(size_t)(bm + r) * Dsz + k0 + c];
        }
        {
            int r = tid >> 4, c = tid & 15;
            sB[r][c] = W[(size_t)(k0 + r) * RANKn + c];
        }
        __syncthreads();
        #pragma unroll
        for (int kk = 0; kk < 16; kk++){
            float b = sB[kk][tx];
            #pragma unroll
            for (int u = 0; u < 4; u++)
                acc[u] += sA[kk][ty*4+u] * b;
        }
        __syncthreads();
    }
    #pragma unroll
    for (int u = 0; u < 4; u++)
        g_bufT[(size_t)(bm + ty*4 + u) * RANKn + tx] = acc[u];
}

// ---------------- gk = log_sigmoid(t @ Wgk2 + bgk) / 16 -----------------------
__global__ void gk_kernel(const float* __restrict__ Wgk2,
                          const float* __restrict__ bgk)
{
    const int col = blockIdx.x * 256 + threadIdx.x;
    const int row = blockIdx.y;
    __shared__ float st[RANKn];
    if (threadIdx.x < RANKn) st[threadIdx.x] = g_bufT[(size_t)row * RANKn + threadIdx.x];
    __syncthreads();
    float acc = bgk[col];
    #pragma unroll
    for (int r = 0; r < RANKn; r++)
        acc += st[r] * Wgk2[r * KDn + col];
    float ls = fminf(acc, 0.0f) - log1pf(expf(-fabsf(acc)));
    g_bufGC[(size_t)row * KDn + col] = ls * (1.0f / 16.0f);
}

// ---------------- per-chunk cumsum of gk along time (in place) ----------------
__global__ void gcum_kernel()
{
    const int ch    = blockIdx.y * 256 + threadIdx.x;
    const int chunk = blockIdx.x;
    const int row0  = chunk * Csz;
    float s = 0.0f;
    for (int t = 0; t < Csz; t++){
        size_t idx = (size_t)(row0 + t) * KDn + ch;
        s += g_bufGC[idx];
        g_bufGC[idx] = s;
    }
}

// ---------------- intra-chunk A = tril( (q*e^g) @ (k*e^-g)^T ) -----------------
__global__ void attnA_kernel()
{
    const int chunk = blockIdx.x;
    const int h     = blockIdx.y;
    const int row0  = chunk * Csz;
    const int cb    = h * DKn;
    const int tid = threadIdx.x;
    const int ty = tid >> 4, tx = tid & 15;
    __shared__ float sq[16][65];
    __shared__ float sk[16][65];
    float acc[4][4] = {};
    for (int k0 = 0; k0 < DKn; k0 += 16){
        #pragma unroll
        for (int rep = 0; rep < 4; rep++){
            int i = tid + rep*256;
            int t = i >> 4, kk = i & 15;
            size_t idx = (size_t)(row0 + t) * KDn + cb + k0 + kk;
            float g = g_bufGC[idx];
            sq[kk][t] = g_bufQ[idx] * expf(g);
            sk[kk][t] = g_bufK[idx] * expf(-g);
        }
        __syncthreads();
        #pragma unroll
        for (int kk = 0; kk < 16; kk++){
            float a[4], b[4];
            #pragma unroll
            for (int u = 0; u < 4; u++){ a[u] = sq[kk][ty*4+u]; b[u] = sk[kk][tx*4+u]; }
            #pragma unroll
            for (int u = 0; u < 4; u++)
                #pragma unroll
                for (int w = 0; w < 4; w++)
                    acc[u][w] += a[u] * b[w];
        }
        __syncthreads();
    }
    #pragma unroll
    for (int u = 0; u < 4; u++)
        #pragma unroll
        for (int w = 0; w < 4; w++){
            int t = ty*4 + u, s = tx*4 + w;
            g_bufA[((size_t)(chunk*Hn + h) * Csz + t) * Csz + s] = (t >= s) ? acc[u][w] : 0.0f;
        }
}

// ---------------- per-chunk kv[k,v] = sum_s k_dec[s,k] * v[s,v] ----------------
__global__ void kv_kernel()
{
    const int chunk = blockIdx.x;
    const int h     = blockIdx.y;
    const int vb    = blockIdx.z;
    const int row0  = chunk * Csz;
    const int kc    = h * DKn;
    const int vc0   = h * DVn + vb * 64;
    const int n     = chunk & 63;
    const int bh    = (chunk >> 6) * Hn + h;
    const int tid = threadIdx.x;
    const int ty = tid >> 4, tx = tid & 15;

    __shared__ float skd[16][128];
    __shared__ float sv [16][65];
    __shared__ float gl [DKn];
    if (tid < DKn) gl[tid] = g_bufGC[(size_t)(row0 + Csz - 1) * KDn + kc + tid];
    __syncthreads();

    float acc[8][4] = {};
    for (int s0 = 0; s0 < Csz; s0 += 16){
        #pragma unroll
        for (int rep = 0; rep < 8; rep++){
            int i = tid + rep*256;
            int ss = i >> 7, kk = i & 127;
            size_t idx = (size_t)(row0 + s0 + ss) * KDn + kc + kk;
            skd[ss][kk] = g_bufK[idx] * expf(gl[kk] - g_bufGC[idx]);
        }
        #pragma unroll
        for (int rep = 0; rep < 4; rep++){
            int i = tid + rep*256;
            int ss = i >> 6, vv = i & 63;
            sv[ss][vv] = g_bufV[(size_t)(row0 + s0 + ss) * VDn + vc0 + vv];
        }
        __syncthreads();
        #pragma unroll
        for (int ss = 0; ss < 16; ss++){
            float a[8], b[4];
            #pragma unroll
            for (int u = 0; u < 8; u++) a[u] = skd[ss][ty*8+u];
            #pragma unroll
            for (int w = 0; w < 4; w++) b[w] = sv[ss][tx*4+w];
            #pragma unroll
            for (int u = 0; u < 8; u++)
                #pragma unroll
                for (int w = 0; w < 4; w++)
                    acc[u][w] += a[u] * b[w];
        }
        __syncthreads();
    }
    size_t base = ((size_t)(bh * NCn + n)) * DKn * DVn;
    #pragma unroll
    for (int u = 0; u < 8; u++)
        #pragma unroll
        for (int w = 0; w < 4; w++)
            g_bufKV[base + (size_t)(ty*8+u) * DVn + vb*64 + tx*4 + w] = acc[u][w];
}

// ---------------- inter-chunk scan (float4): S_0=0; S_{n+1}=S_n*e^{gl}+kv ------
__global__ void scan_kernel()
{
    const int bh    = blockIdx.x;                       // 0..7
    const int elem4 = blockIdx.y * 256 + threadIdx.x;   // 0..8191 (float4 index)
    const int kk    = elem4 >> 6;                       // (elem4*4)>>8
    const int b     = bh / Hn, h = bh % Hn;
    float4 s = make_float4(0.f, 0.f, 0.f, 0.f);
    for (int n = 0; n < NCn; n++){
        size_t base4 = ((size_t)(bh * NCn + n)) * (DKn * DVn / 4);
        ((float4*)g_bufS)[base4 + elem4] = s;
        float e = expf(g_bufGC[(size_t)((b * NCn + n) * Csz + Csz - 1) * KDn + h * DKn + kk]);
        float4 kv = ((const float4*)g_bufKV)[base4 + elem4];
        s.x = s.x * e + kv.x;
        s.y = s.y * e + kv.y;
        s.z = s.z * e + kv.z;
        s.w = s.w * e + kv.w;
    }
}

// ---------------- o = A @ v_chunk + q_t @ S_n ----------------------------------
__global__ void out_kernel()
{
    const int chunk = blockIdx.x;
    const int h     = blockIdx.y;
    const int vb    = blockIdx.z;
    const int row0  = chunk * Csz;
    const int n     = chunk & 63;
    const int bh    = (chunk >> 6) * Hn + h;
    const int vcol  = h * DVn + vb * 64;
    const int tid = threadIdx.x;
    const int ty = tid >> 4, tx = tid & 15;

    __shared__ float sa[16][65];
    __shared__ float sb[16][65];
    float acc[4][4] = {};

    for (int s0 = 0; s0 < Csz; s0 += 16){
        #pragma unroll
        for (int rep = 0; rep < 4; rep++){
            int i = tid + rep*256;
            int t = i >> 4, ss = i & 15;
            sa[ss][t] = g_bufA[((size_t)(chunk*Hn + h) * Csz + t) * Csz + s0 + ss];
        }
        #pragma unroll
        for (int rep = 0; rep < 4; rep++){
            int i = tid + rep*256;
            int ss = i >> 6, vv = i & 63;
            sb[ss][vv] = g_bufV[(size_t)(row0 + s0 + ss) * VDn + vcol + vv];
        }
        __syncthreads();
        #pragma unroll
        for (int ss = 0; ss < 16; ss++){
            float a[4], b[4];
            #pragma unroll
            for (int u = 0; u < 4; u++){ a[u] = sa[ss][ty*4+u]; b[u] = sb[ss][tx*4+u]; }
            #pragma unroll
            for (int u = 0; u < 4; u++)
                #pragma unroll
                for (int w = 0; w < 4; w++)
                    acc[u][w] += a[u] * b[w];
        }
        __syncthreads();
    }

    const size_t sbase = ((size_t)(bh * NCn + n)) * (DKn * DVn);
    for (int k0 = 0; k0 < DKn; k0 += 16){
        #pragma unroll
        for (int rep = 0; rep < 4; rep++){
            int i = tid + rep*256;
            int t = i >> 4, kk = i & 15;
            size_t idx = (size_t)(row0 + t) * KDn + h * DKn + k0 + kk;
            sa[kk][t] = g_bufQ[idx] * expf(g_bufGC[idx]);
        }
        #pragma unroll
        for (int rep = 0; rep < 4; rep++){
            int i = tid + rep*256;
            int kk = i >> 6, vv = i & 63;
            sb[kk][vv] = g_bufS[sbase + (size_t)(k0 + kk) * DVn + vb*64 + vv];
        }
        __syncthreads();
        #pragma unroll
        for (int kk = 0; kk < 16; kk++){
            float a[4], b[4];
            #pragma unroll
            for (int u = 0; u < 4; u++){ a[u] = sa[kk][ty*4+u]; b[u] = sb[kk][tx*4+u]; }
            #pragma unroll
            for (int u = 0; u < 4; u++)
                #pragma unroll
                for (int w = 0; w < 4; w++)
                    acc[u][w] += a[u] * b[w];
        }
        __syncthreads();
    }

    #pragma unroll
    for (int u = 0; u < 4; u++)
        #pragma unroll
        for (int w = 0; w < 4; w++)
            g_bufO[(size_t)(row0 + ty*4 + u) * VDn + vcol + tx*4 + w] = acc[u][w];
}

// ---------------- RMS-norm over DV + SiLU gate (norm_w shape (DV,)) ------------
__global__ void norm_gate_kernel(const float* __restrict__ norm_w)
{
    const int row = blockIdx.x;
    const int h   = blockIdx.y;
    const int tid = threadIdx.x;   // 256 == DVn
    size_t idx = (size_t)row * VDn + h * DVn + tid;
    float o = g_bufO[idx];
    float sq = o * o;
    #pragma unroll
    for (int off = 16; off; off >>= 1) sq += __shfl_xor_sync(0xffffffffu, sq, off);
    __shared__ float ws[8];
    if ((tid & 31) == 0) ws[tid >> 5] = sq;
    __syncthreads();
    float tot = 0.0f;
    #pragma unroll
    for (int i = 0; i < 8; i++) tot += ws[i];
    float r = rsqrtf(tot * (1.0f / 256.0f) + 1e-5f);
    float gv = g_bufG[idx];
    float silu = gv / (1.0f + expf(-gv));
    g_bufZ[idx] = o * r * norm_w[tid] * silu;
}

// ---------------- launcher ------------------------------------------------------
extern "C" void kernel_launch(void* const* d_in, const int* in_sizes, int n_in,
                              void* d_out, int out_size)
{
    const float* x     = (const float*)d_in[0];
    const float* Wq    = (const float*)d_in[1];
    const float* Wk    = (const float*)d_in[2];
    const float* Wv    = (const float*)d_in[3];
    const float* Wgk1  = (const float*)d_in[4];
    const float* Wgk2  = (const float*)d_in[5];
    const float* bgk   = (const float*)d_in[6];
    const float* Wg    = (const float*)d_in[7];
    const float* Wo    = (const float*)d_in[8];
    const float* normw = (const float*)d_in[9];
    float* out = (float*)d_out;

    const float scale = 0.08838834764831845f;   // 1/sqrt(128)
    dim3 blk(256);
    const int smem_bytes = SMEM_FLOATS * 4;     // ~71.7 KB

    cudaFuncSetAttribute(tf32_proj_kernel,
                         cudaFuncAttributeMaxDynamicSharedMemorySize, smem_bytes);
    cudaFuncSetAttribute(tf32_final_kernel,
                         cudaFuncAttributeMaxDynamicSharedMemorySize, smem_bytes);

    // projections on the tensor pipe (TF32, cp.async pipelined)
    tf32_proj_kernel<<<dim3(KDn/128, NROWS/128), blk, smem_bytes>>>(x, Wq, 0, KDn, scale);
    tf32_proj_kernel<<<dim3(KDn/128, NROWS/128), blk, smem_bytes>>>(x, Wk, 1, KDn, 1.0f);
    tf32_proj_kernel<<<dim3(VDn/128, NROWS/128), blk, smem_bytes>>>(x, Wv, 2, VDn, 1.0f);
    tf32_proj_kernel<<<dim3(VDn/128, NROWS/128), blk, smem_bytes>>>(x, Wg, 3, VDn, 1.0f);

    // low-rank gate path
    gemm_t_kernel<<<NROWS/64, blk>>>(x, Wgk1);
    gk_kernel<<<dim3(KDn/256, NROWS), blk>>>(Wgk2, bgk);
    gcum_kernel<<<dim3(Bsz*NCn, KDn/256), blk>>>();

    // GLA chunks
    attnA_kernel<<<dim3(Bsz*NCn, Hn), blk>>>();
    kv_kernel<<<dim3(Bsz*NCn, Hn, DVn/64), blk>>>();
    scan_kernel<<<dim3(Bsz*Hn, (DKn*DVn)/4/256), blk>>>();
    out_kernel<<<dim3(Bsz*NCn, Hn, DVn/64), blk>>>();

    // epilogue
    norm_gate_kernel<<<dim3(NROWS, Hn), blk>>>(normw);
    tf32_final_kernel<<<dim3(Dsz/128, NROWS/128), blk, smem_bytes>>>(Wo, out);
}